// round 14
// baseline (speedup 1.0000x reference)
#include <cuda_runtime.h>
#include <cuda_bf16.h>
#include <cuda_fp16.h>
#include <cstdint>

#define IN_F 256
#define HID  128
#define TILE_M 128
#define MAX_NODES 50000
#define MAX_EDGES 800000
#define KCH      32               // K per pipeline stage
#define NCH      (IN_F / KCH)     // 8 stages
#define SSTRIDE  36               // smem row stride in floats (36 % 32 == 4)
#define CAP      128              // bucket capacity per row (deg~Poisson(16))

// Scratch (device globals; no device-memory allocation APIs anywhere).
// INVARIANT: g_cnt is all-zero at kernel_launch entry; gather re-zeroes it.
__device__ __half g_support_h[MAX_NODES * HID];   // fp16 support
__device__ int    g_cnt[MAX_NODES];               // per-row edge count
__device__ int2   g_bucket[MAX_NODES * CAP];      // (col, val) per row slot

// ---------------------------------------------------------------------------
// Helpers (plain sm_80-era PTX; nothing arch-'a' gated)
// ---------------------------------------------------------------------------
__device__ __forceinline__ uint32_t smem_to_u32(const void* p) {
    uint32_t a;
    asm("{ .reg .u64 t; cvta.to.shared.u64 t, %1; cvt.u32.u64 %0, t; }"
        : "=r"(a) : "l"(p));
    return a;
}

__device__ __forceinline__ uint32_t f2tf32(float f) {
    uint32_t r;
    asm("cvt.rna.tf32.f32 %0, %1;" : "=r"(r) : "f"(f));
    return r;
}

__device__ __forceinline__ void mma_tf32(float* c, const uint32_t* a,
                                         uint32_t b0, uint32_t b1) {
    asm volatile("mma.sync.aligned.m16n8k8.row.col.f32.tf32.tf32.f32 "
        "{%0,%1,%2,%3}, {%4,%5,%6,%7}, {%8,%9}, {%0,%1,%2,%3};"
        : "+f"(c[0]), "+f"(c[1]), "+f"(c[2]), "+f"(c[3])
        : "r"(a[0]), "r"(a[1]), "r"(a[2]), "r"(a[3]), "r"(b0), "r"(b1));
}

#define CP_ASYNC16(dst, src) \
    asm volatile("cp.async.cg.shared.global [%0], [%1], 16;" \
                 :: "r"(dst), "l"(src) : "memory")
#define CP_ASYNC16G(dst, src, sz) \
    asm volatile("cp.async.cg.shared.global [%0], [%1], 16, %2;" \
                 :: "r"(dst), "l"(src), "r"(sz) : "memory")
#define CP_COMMIT() asm volatile("cp.async.commit_group;" ::: "memory")
#define CP_WAIT(n)  asm volatile("cp.async.wait_group %0;" :: "n"(n) : "memory")

#define HALF_STAGE (TILE_M * SSTRIDE * 4)     // 18432 B (one of A or B)
#define STAGE_BYTES (2 * HALF_STAGE)          // 36864 B (A + B)
#define GEMM_SMEM (2 * STAGE_BYTES)           // 73728 B, occ 2

// ---------------------------------------------------------------------------
// GEMM: support = x @ W^T + b via single-pass tf32 mma (m16n8k8),
// two-stage cp.async pipeline over 8 K-chunks of 32. W streamed raw;
// both A and B converted to tf32 at register load (rna).
// ---------------------------------------------------------------------------
__global__ __launch_bounds__(256, 2) void gcn_linear_tf32_kernel(
    const float* __restrict__ x,
    const float* __restrict__ W,
    const float* __restrict__ b,
    int n_nodes)
{
    extern __shared__ char smem[];
    const uint32_t sbase = smem_to_u32(smem);

    const int t    = threadIdx.x;
    const int wid  = t >> 5;
    const int lane = t & 31;
    const int gid  = lane >> 2;          // 0..7
    const int tig  = lane & 3;           // 0..3
    const int row0 = blockIdx.x * TILE_M;

    const int wm = (wid & 3) * 32;
    const int wn = (wid >> 2) * 64;

    float acc[2][8][4];
#pragma unroll
    for (int mt = 0; mt < 2; mt++)
#pragma unroll
        for (int nt = 0; nt < 8; nt++)
#pragma unroll
            for (int j = 0; j < 4; j++) acc[mt][nt][j] = 0.0f;

    auto issue = [&](int c, int s) {
        uint32_t aBase = sbase + (uint32_t)s * STAGE_BYTES;
        uint32_t bBase = aBase + HALF_STAGE;
#pragma unroll
        for (int i = 0; i < 4; i++) {
            int idx = t + i * 256;              // 0..1023
            int n   = idx >> 3;                 // tile row 0..127
            int kq  = idx & 7;                  // float4 group 0..7
            uint32_t doff = (uint32_t)(n * SSTRIDE + kq * 4) * 4;
            int grow = row0 + n;
            const float* asrc = x + (size_t)grow * IN_F + c * KCH + kq * 4;
            int asz = (grow < n_nodes) ? 16 : 0;
            CP_ASYNC16G(aBase + doff, asrc, asz);
            const float* bsrc = W + n * IN_F + c * KCH + kq * 4;
            CP_ASYNC16(bBase + doff, bsrc);
        }
        CP_COMMIT();
    };

    issue(0, 0);

    for (int c = 0; c < NCH; c++) {
        const int cur = c & 1;
        if (c + 1 < NCH) {
            issue(c + 1, cur ^ 1);
            CP_WAIT(1);
        } else {
            CP_WAIT(0);
        }
        __syncthreads();

        const float* As = (const float*)(smem + (size_t)cur * STAGE_BYTES);
        const float* Bs = (const float*)(smem + (size_t)cur * STAGE_BYTES + HALF_STAGE);

#pragma unroll
        for (int ks = 0; ks < KCH / 8; ks++) {   // 4 K8 steps
            uint32_t a[2][4];
#pragma unroll
            for (int mt = 0; mt < 2; mt++) {
                int r0 = wm + mt * 16 + gid;
                int kc = ks * 8 + tig;
                a[mt][0] = f2tf32(As[r0 * SSTRIDE + kc]);
                a[mt][1] = f2tf32(As[(r0 + 8) * SSTRIDE + kc]);
                a[mt][2] = f2tf32(As[r0 * SSTRIDE + kc + 4]);
                a[mt][3] = f2tf32(As[(r0 + 8) * SSTRIDE + kc + 4]);
            }
#pragma unroll
            for (int ng = 0; ng < 8; ng++) {
                int nr = wn + ng * 8 + gid;
                int kc = ks * 8 + tig;
                uint32_t b0 = f2tf32(Bs[nr * SSTRIDE + kc]);
                uint32_t b1 = f2tf32(Bs[nr * SSTRIDE + kc + 4]);
                mma_tf32(acc[0][ng], a[0], b0, b1);
                mma_tf32(acc[1][ng], a[1], b0, b1);
            }
        }
        __syncthreads();
    }

    // ---- epilogue: bias + fp16 store (C frag: rows gid/gid+8, cols 2*tig) ----
#pragma unroll
    for (int nt = 0; nt < 8; nt++) {
        int col = wn + nt * 8 + 2 * tig;
        float2 bb = *(const float2*)(b + col);
#pragma unroll
        for (int mt = 0; mt < 2; mt++) {
            int r0g = row0 + wm + mt * 16 + gid;
            if (r0g < n_nodes) {
                __half2 h0 = __floats2half2_rn(acc[mt][nt][0] + bb.x,
                                               acc[mt][nt][1] + bb.y);
                *(__half2*)(g_support_h + (size_t)r0g * HID + col) = h0;
            }
            int r1g = r0g + 8;
            if (r1g < n_nodes) {
                __half2 h1 = __floats2half2_rn(acc[mt][nt][2] + bb.x,
                                               acc[mt][nt][3] + bb.y);
                *(__half2*)(g_support_h + (size_t)r1g * HID + col) = h1;
            }
        }
    }
}

// ---------------------------------------------------------------------------
// fill: direct bucket scatter — no hist/scan needed. 4 edges/thread.
// pos = atomicAdd(cnt[r]); bucket[r*CAP + pos] = (col, val).
// ---------------------------------------------------------------------------
__global__ __launch_bounds__(256) void fill_kernel(
    const int*   __restrict__ adj_row,
    const int*   __restrict__ adj_col,
    const float* __restrict__ adj_val,
    int n_edges)
{
    int base = (blockIdx.x * blockDim.x + threadIdx.x) * 4;
    if (base + 3 < n_edges) {
        int4   r = *(const int4*)(adj_row + base);
        int4   c = *(const int4*)(adj_col + base);
        float4 v = *(const float4*)(adj_val + base);
        int p0 = atomicAdd(&g_cnt[r.x], 1);
        int p1 = atomicAdd(&g_cnt[r.y], 1);
        int p2 = atomicAdd(&g_cnt[r.z], 1);
        int p3 = atomicAdd(&g_cnt[r.w], 1);
        if (p0 < CAP) g_bucket[((size_t)r.x << 7) + p0] = make_int2(c.x, __float_as_int(v.x));
        if (p1 < CAP) g_bucket[((size_t)r.y << 7) + p1] = make_int2(c.y, __float_as_int(v.y));
        if (p2 < CAP) g_bucket[((size_t)r.z << 7) + p2] = make_int2(c.z, __float_as_int(v.z));
        if (p3 < CAP) g_bucket[((size_t)r.w << 7) + p3] = make_int2(c.w, __float_as_int(v.w));
    } else {
        for (int e = base; e < n_edges; e++) {
            int r   = adj_row[e];
            int pos = atomicAdd(&g_cnt[r], 1);
            if (pos < CAP)
                g_bucket[((size_t)r << 7) + pos] =
                    make_int2(adj_col[e], __float_as_int(adj_val[e]));
        }
    }
}

// ---------------------------------------------------------------------------
// gather: warp per row, half-warp per edge (16 lanes x uint4 = 256B row),
// shfl_xor(16) merge, no value atomics. Re-zeroes g_cnt (invariant).
// ---------------------------------------------------------------------------
__global__ __launch_bounds__(256) void row_gather_kernel(
    float* __restrict__ out, int n_nodes)
{
    const int row  = (blockIdx.x * blockDim.x + threadIdx.x) >> 5;
    const int lane = threadIdx.x & 31;
    const int half = lane >> 4;
    const int hl   = lane & 15;
    if (row >= n_nodes) return;

    int cnt = g_cnt[row];
    if (cnt > CAP) cnt = CAP;
    if (lane == 0) g_cnt[row] = 0;       // restore zero-invariant

    const int s0 = 0;
    const int s1 = cnt;
    const int2* bucket = g_bucket + ((size_t)row << 7);

    const uint4* sup = reinterpret_cast<const uint4*>(g_support_h);
    float acc[8];
#pragma unroll
    for (int j = 0; j < 8; j++) acc[j] = 0.0f;

    int e = s0 + half;
    for (; e + 2 < s1; e += 4) {
        int2 ev0 = bucket[e];
        int2 ev1 = bucket[e + 2];
        uint4 r0 = sup[(size_t)ev0.x * 16 + hl];
        uint4 r1 = sup[(size_t)ev1.x * 16 + hl];
        float v0 = __int_as_float(ev0.y);
        float v1 = __int_as_float(ev1.y);
        float2 p0 = __half22float2(*(const __half2*)&r0.x);
        float2 p1 = __half22float2(*(const __half2*)&r0.y);
        float2 p2 = __half22float2(*(const __half2*)&r0.z);
        float2 p3 = __half22float2(*(const __half2*)&r0.w);
        float2 q0 = __half22float2(*(const __half2*)&r1.x);
        float2 q1 = __half22float2(*(const __half2*)&r1.y);
        float2 q2 = __half22float2(*(const __half2*)&r1.z);
        float2 q3 = __half22float2(*(const __half2*)&r1.w);
        acc[0] += v0 * p0.x + v1 * q0.x;
        acc[1] += v0 * p0.y + v1 * q0.y;
        acc[2] += v0 * p1.x + v1 * q1.x;
        acc[3] += v0 * p1.y + v1 * q1.y;
        acc[4] += v0 * p2.x + v1 * q2.x;
        acc[5] += v0 * p2.y + v1 * q2.y;
        acc[6] += v0 * p3.x + v1 * q3.x;
        acc[7] += v0 * p3.y + v1 * q3.y;
    }
    for (; e < s1; e += 2) {
        int2 ev = bucket[e];
        uint4 r0 = sup[(size_t)ev.x * 16 + hl];
        float v = __int_as_float(ev.y);
        float2 p0 = __half22float2(*(const __half2*)&r0.x);
        float2 p1 = __half22float2(*(const __half2*)&r0.y);
        float2 p2 = __half22float2(*(const __half2*)&r0.z);
        float2 p3 = __half22float2(*(const __half2*)&r0.w);
        acc[0] += v * p0.x; acc[1] += v * p0.y;
        acc[2] += v * p1.x; acc[3] += v * p1.y;
        acc[4] += v * p2.x; acc[5] += v * p2.y;
        acc[6] += v * p3.x; acc[7] += v * p3.y;
    }

#pragma unroll
    for (int j = 0; j < 8; j++)
        acc[j] += __shfl_xor_sync(0xffffffffu, acc[j], 16);

    if (half == 0) {
        float4* o = reinterpret_cast<float4*>(out + (size_t)row * HID + hl * 8);
        o[0] = make_float4(acc[0], acc[1], acc[2], acc[3]);
        o[1] = make_float4(acc[4], acc[5], acc[6], acc[7]);
    }
}

// ---------------------------------------------------------------------------
// Side stream + events, created ONCE (no device-mem allocation APIs).
// ---------------------------------------------------------------------------
struct AuxStreams {
    cudaStream_t s  = nullptr;
    cudaEvent_t  e1 = nullptr, e2 = nullptr;
    bool ok = false;
    AuxStreams() {
        if (cudaStreamCreateWithFlags(&s, cudaStreamNonBlocking) != cudaSuccess) { s = nullptr; return; }
        if (cudaEventCreateWithFlags(&e1, cudaEventDisableTiming) != cudaSuccess) { e1 = nullptr; return; }
        if (cudaEventCreateWithFlags(&e2, cudaEventDisableTiming) != cudaSuccess) { e2 = nullptr; return; }
        ok = true;
    }
};
static AuxStreams g_aux;

// ---------------------------------------------------------------------------
// Launch: inputs: x, adj_row, adj_col, adj_val, W, b
// Graph:  main: gemm ---.-> gather
//         side: fill ---'
// ---------------------------------------------------------------------------
extern "C" void kernel_launch(void* const* d_in, const int* in_sizes, int n_in,
                              void* d_out, int out_size)
{
    const float* x       = (const float*)d_in[0];
    const int*   adj_row = (const int*)  d_in[1];
    const int*   adj_col = (const int*)  d_in[2];
    const float* adj_val = (const float*)d_in[3];
    const float* W       = (const float*)d_in[4];
    const float* b       = (const float*)d_in[5];
    float*       out     = (float*)d_out;

    const int n_nodes = in_sizes[0] / IN_F;
    const int n_edges = in_sizes[1];
    const int gemm_blocks = (n_nodes + TILE_M - 1) / TILE_M;

    cudaFuncSetAttribute(gcn_linear_tf32_kernel,
                         cudaFuncAttributeMaxDynamicSharedMemorySize, GEMM_SMEM);

    const bool par = g_aux.ok;
    cudaStream_t sbin = par ? g_aux.s : (cudaStream_t)0;

    if (par) {
        cudaEventRecord(g_aux.e1, 0);
        cudaStreamWaitEvent(sbin, g_aux.e1, 0);
    }

    gcn_linear_tf32_kernel<<<gemm_blocks, 256, GEMM_SMEM>>>(x, W, b, n_nodes);

    fill_kernel<<<(n_edges / 4 + 255) / 256, 256, 0, sbin>>>(adj_row, adj_col, adj_val, n_edges);

    if (par) {
        cudaEventRecord(g_aux.e2, sbin);
        cudaStreamWaitEvent(0, g_aux.e2, 0);
    }

    row_gather_kernel<<<(n_nodes * 32 + 255) / 256, 256>>>(out, n_nodes);
}

// round 16
// speedup vs baseline: 1.7965x; 1.7965x over previous
#include <cuda_runtime.h>
#include <cuda_bf16.h>
#include <cuda_fp16.h>
#include <cstdint>

#define IN_F 256
#define HID  128
#define TILE_M 128
#define MAX_NODES 50000
#define MAX_EDGES 800000
#define SCAN_B   256
#define KCH      32               // K per pipeline stage
#define NCH      (IN_F / KCH)     // 8 stages
#define SSTRIDE  36               // smem row stride in floats (36 % 32 == 4)

// Scratch (device globals; no device-memory allocation APIs anywhere).
// INVARIANT: g_cnt is all-zero at kernel_launch entry; the GATHER kernel
// (which runs after binning completes) re-zeroes it — the scan only reads.
__device__ __half g_support_h[MAX_NODES * HID];   // fp16 support
__device__ int    g_cnt[MAX_NODES];
__device__ int    g_row_start[MAX_NODES + 1];
__device__ int    g_cursor[MAX_NODES];
__device__ int2   g_edge[MAX_EDGES];

// ---------------------------------------------------------------------------
// Helpers (plain sm_80-era PTX; nothing arch-'a' gated)
// ---------------------------------------------------------------------------
__device__ __forceinline__ uint32_t smem_to_u32(const void* p) {
    uint32_t a;
    asm("{ .reg .u64 t; cvta.to.shared.u64 t, %1; cvt.u32.u64 %0, t; }"
        : "=r"(a) : "l"(p));
    return a;
}

__device__ __forceinline__ uint32_t f2tf32(float f) {
    uint32_t r;
    asm("cvt.rna.tf32.f32 %0, %1;" : "=r"(r) : "f"(f));
    return r;
}

__device__ __forceinline__ void mma_tf32(float* c, const uint32_t* a,
                                         uint32_t b0, uint32_t b1) {
    asm volatile("mma.sync.aligned.m16n8k8.row.col.f32.tf32.tf32.f32 "
        "{%0,%1,%2,%3}, {%4,%5,%6,%7}, {%8,%9}, {%0,%1,%2,%3};"
        : "+f"(c[0]), "+f"(c[1]), "+f"(c[2]), "+f"(c[3])
        : "r"(a[0]), "r"(a[1]), "r"(a[2]), "r"(a[3]), "r"(b0), "r"(b1));
}

#define CP_ASYNC16(dst, src) \
    asm volatile("cp.async.cg.shared.global [%0], [%1], 16;" \
                 :: "r"(dst), "l"(src) : "memory")
#define CP_ASYNC16G(dst, src, sz) \
    asm volatile("cp.async.cg.shared.global [%0], [%1], 16, %2;" \
                 :: "r"(dst), "l"(src), "r"(sz) : "memory")
#define CP_COMMIT() asm volatile("cp.async.commit_group;" ::: "memory")
#define CP_WAIT(n)  asm volatile("cp.async.wait_group %0;" :: "n"(n) : "memory")

#define HALF_STAGE (TILE_M * SSTRIDE * 4)     // 18432 B (one of A or B)
#define STAGE_BYTES (2 * HALF_STAGE)          // 36864 B (A + B)
#define GEMM_SMEM (2 * STAGE_BYTES)           // 73728 B, occ 2

// ---------------------------------------------------------------------------
// GEMM: support = x @ W^T + b via single-pass tf32 mma (m16n8k8),
// two-stage cp.async pipeline over 8 K-chunks of 32. W streamed raw;
// both A and B converted to tf32 at register load (rna).
// ---------------------------------------------------------------------------
__global__ __launch_bounds__(256, 2) void gcn_linear_tf32_kernel(
    const float* __restrict__ x,
    const float* __restrict__ W,
    const float* __restrict__ b,
    int n_nodes)
{
    extern __shared__ char smem[];
    const uint32_t sbase = smem_to_u32(smem);

    const int t    = threadIdx.x;
    const int wid  = t >> 5;
    const int lane = t & 31;
    const int gid  = lane >> 2;          // 0..7
    const int tig  = lane & 3;           // 0..3
    const int row0 = blockIdx.x * TILE_M;

    const int wm = (wid & 3) * 32;
    const int wn = (wid >> 2) * 64;

    float acc[2][8][4];
#pragma unroll
    for (int mt = 0; mt < 2; mt++)
#pragma unroll
        for (int nt = 0; nt < 8; nt++)
#pragma unroll
            for (int j = 0; j < 4; j++) acc[mt][nt][j] = 0.0f;

    auto issue = [&](int c, int s) {
        uint32_t aBase = sbase + (uint32_t)s * STAGE_BYTES;
        uint32_t bBase = aBase + HALF_STAGE;
#pragma unroll
        for (int i = 0; i < 4; i++) {
            int idx = t + i * 256;              // 0..1023
            int n   = idx >> 3;                 // tile row 0..127
            int kq  = idx & 7;                  // float4 group 0..7
            uint32_t doff = (uint32_t)(n * SSTRIDE + kq * 4) * 4;
            int grow = row0 + n;
            const float* asrc = x + (size_t)grow * IN_F + c * KCH + kq * 4;
            int asz = (grow < n_nodes) ? 16 : 0;
            CP_ASYNC16G(aBase + doff, asrc, asz);
            const float* bsrc = W + n * IN_F + c * KCH + kq * 4;
            CP_ASYNC16(bBase + doff, bsrc);
        }
        CP_COMMIT();
    };

    issue(0, 0);

    for (int c = 0; c < NCH; c++) {
        const int cur = c & 1;
        if (c + 1 < NCH) {
            issue(c + 1, cur ^ 1);
            CP_WAIT(1);
        } else {
            CP_WAIT(0);
        }
        __syncthreads();

        const float* As = (const float*)(smem + (size_t)cur * STAGE_BYTES);
        const float* Bs = (const float*)(smem + (size_t)cur * STAGE_BYTES + HALF_STAGE);

#pragma unroll
        for (int ks = 0; ks < KCH / 8; ks++) {   // 4 K8 steps
            uint32_t a[2][4];
#pragma unroll
            for (int mt = 0; mt < 2; mt++) {
                int r0 = wm + mt * 16 + gid;
                int kc = ks * 8 + tig;
                a[mt][0] = f2tf32(As[r0 * SSTRIDE + kc]);
                a[mt][1] = f2tf32(As[(r0 + 8) * SSTRIDE + kc]);
                a[mt][2] = f2tf32(As[r0 * SSTRIDE + kc + 4]);
                a[mt][3] = f2tf32(As[(r0 + 8) * SSTRIDE + kc + 4]);
            }
#pragma unroll
            for (int ng = 0; ng < 8; ng++) {
                int nr = wn + ng * 8 + gid;
                int kc = ks * 8 + tig;
                uint32_t b0 = f2tf32(Bs[nr * SSTRIDE + kc]);
                uint32_t b1 = f2tf32(Bs[nr * SSTRIDE + kc + 4]);
                mma_tf32(acc[0][ng], a[0], b0, b1);
                mma_tf32(acc[1][ng], a[1], b0, b1);
            }
        }
        __syncthreads();
    }

    // ---- epilogue: bias + fp16 store (C frag: rows gid/gid+8, cols 2*tig) ----
#pragma unroll
    for (int nt = 0; nt < 8; nt++) {
        int col = wn + nt * 8 + 2 * tig;
        float2 bb = *(const float2*)(b + col);
#pragma unroll
        for (int mt = 0; mt < 2; mt++) {
            int r0g = row0 + wm + mt * 16 + gid;
            if (r0g < n_nodes) {
                __half2 h0 = __floats2half2_rn(acc[mt][nt][0] + bb.x,
                                               acc[mt][nt][1] + bb.y);
                *(__half2*)(g_support_h + (size_t)r0g * HID + col) = h0;
            }
            int r1g = r0g + 8;
            if (r1g < n_nodes) {
                __half2 h1 = __floats2half2_rn(acc[mt][nt][2] + bb.x,
                                               acc[mt][nt][3] + bb.y);
                *(__half2*)(g_support_h + (size_t)r1g * HID + col) = h1;
            }
        }
    }
}

// ---------------------------------------------------------------------------
// hist: int4-vectorized edge histogram (4 edges/thread)
// ---------------------------------------------------------------------------
__global__ __launch_bounds__(256) void hist_kernel(
    const int* __restrict__ adj_row, int n_edges)
{
    int base = (blockIdx.x * blockDim.x + threadIdx.x) * 4;
    if (base + 3 < n_edges) {
        int4 r = *(const int4*)(adj_row + base);
        atomicAdd(&g_cnt[r.x], 1);
        atomicAdd(&g_cnt[r.y], 1);
        atomicAdd(&g_cnt[r.z], 1);
        atomicAdd(&g_cnt[r.w], 1);
    } else {
        for (int e = base; e < n_edges; e++)
            atomicAdd(&g_cnt[adj_row[e]], 1);
    }
}

// ---------------------------------------------------------------------------
// scan (fused, single kernel, READ-ONLY on g_cnt — no cross-block race):
// each block computes its exclusive block prefix by thread-strided sum over
// preceding chunks, then local inclusive scan; writes row_start/cursor.
// g_cnt is re-zeroed later by the gather kernel (strictly ordered after).
// ---------------------------------------------------------------------------
__global__ __launch_bounds__(SCAN_B) void scan_fused_kernel(int n_sb, int n_nodes)
{
    __shared__ int sm[SCAN_B];
    __shared__ int wsum[SCAN_B / 32];
    __shared__ int s_prefix;
    const int t   = threadIdx.x;
    const int nb  = blockIdx.x;
    const int idx = nb * SCAN_B + t;

    // exclusive prefix over preceding chunks (pure reads)
    int partial = 0;
    const int lim = nb * SCAN_B;
    for (int j = t; j < lim; j += SCAN_B) partial += g_cnt[j];
#pragma unroll
    for (int o = 16; o > 0; o >>= 1)
        partial += __shfl_down_sync(0xffffffffu, partial, o);
    if ((t & 31) == 0) wsum[t >> 5] = partial;
    __syncthreads();
    if (t < 32) {
        int s = (t < SCAN_B / 32) ? wsum[t] : 0;
#pragma unroll
        for (int o = 4; o > 0; o >>= 1)
            s += __shfl_down_sync(0xffffffffu, s, o);
        if (t == 0) s_prefix = s;
    }

    // local inclusive scan of own chunk
    int v = (idx < n_nodes) ? g_cnt[idx] : 0;
    sm[t] = v;
    __syncthreads();
#pragma unroll
    for (int o = 1; o < SCAN_B; o <<= 1) {
        int u = (t >= o) ? sm[t - o] : 0;
        __syncthreads();
        sm[t] += u;
        __syncthreads();
    }

    const int blk_prefix = s_prefix;
    if (idx < n_nodes) {
        int excl = blk_prefix + sm[t] - v;
        g_row_start[idx] = excl;
        g_cursor[idx]    = excl;
    }
    if (nb == n_sb - 1 && t == 0)
        g_row_start[n_nodes] = blk_prefix + sm[SCAN_B - 1];
}

// ---------------------------------------------------------------------------
// fill: int4-vectorized (4 edges/thread, independent atomic chains)
// ---------------------------------------------------------------------------
__global__ __launch_bounds__(256) void fill_kernel(
    const int*   __restrict__ adj_row,
    const int*   __restrict__ adj_col,
    const float* __restrict__ adj_val,
    int n_edges)
{
    int base = (blockIdx.x * blockDim.x + threadIdx.x) * 4;
    if (base + 3 < n_edges) {
        int4   r = *(const int4*)(adj_row + base);
        int4   c = *(const int4*)(adj_col + base);
        float4 v = *(const float4*)(adj_val + base);
        int p0 = atomicAdd(&g_cursor[r.x], 1);
        int p1 = atomicAdd(&g_cursor[r.y], 1);
        int p2 = atomicAdd(&g_cursor[r.z], 1);
        int p3 = atomicAdd(&g_cursor[r.w], 1);
        g_edge[p0] = make_int2(c.x, __float_as_int(v.x));
        g_edge[p1] = make_int2(c.y, __float_as_int(v.y));
        g_edge[p2] = make_int2(c.z, __float_as_int(v.z));
        g_edge[p3] = make_int2(c.w, __float_as_int(v.w));
    } else {
        for (int e = base; e < n_edges; e++) {
            int r   = adj_row[e];
            int pos = atomicAdd(&g_cursor[r], 1);
            g_edge[pos] = make_int2(adj_col[e], __float_as_int(adj_val[e]));
        }
    }
}

// ---------------------------------------------------------------------------
// gather: warp per row, half-warp per edge (16 lanes x uint4 = 256B row),
// shfl_xor(16) merge, no atomics. Lane 0 re-zeroes g_cnt[row] (restores the
// zero-invariant; this kernel is ordered after all g_cnt readers).
// ---------------------------------------------------------------------------
__global__ __launch_bounds__(256) void row_gather_kernel(
    float* __restrict__ out, int n_nodes)
{
    const int row  = (blockIdx.x * blockDim.x + threadIdx.x) >> 5;
    const int lane = threadIdx.x & 31;
    const int half = lane >> 4;
    const int hl   = lane & 15;
    if (row >= n_nodes) return;

    if (lane == 0) g_cnt[row] = 0;       // restore zero-invariant

    const int s0 = g_row_start[row];
    const int s1 = g_row_start[row + 1];

    const uint4* sup = reinterpret_cast<const uint4*>(g_support_h);
    float acc[8];
#pragma unroll
    for (int j = 0; j < 8; j++) acc[j] = 0.0f;

    int e = s0 + half;
    for (; e + 2 < s1; e += 4) {
        int2 ev0 = g_edge[e];
        int2 ev1 = g_edge[e + 2];
        uint4 r0 = sup[(size_t)ev0.x * 16 + hl];
        uint4 r1 = sup[(size_t)ev1.x * 16 + hl];
        float v0 = __int_as_float(ev0.y);
        float v1 = __int_as_float(ev1.y);
        float2 p0 = __half22float2(*(const __half2*)&r0.x);
        float2 p1 = __half22float2(*(const __half2*)&r0.y);
        float2 p2 = __half22float2(*(const __half2*)&r0.z);
        float2 p3 = __half22float2(*(const __half2*)&r0.w);
        float2 q0 = __half22float2(*(const __half2*)&r1.x);
        float2 q1 = __half22float2(*(const __half2*)&r1.y);
        float2 q2 = __half22float2(*(const __half2*)&r1.z);
        float2 q3 = __half22float2(*(const __half2*)&r1.w);
        acc[0] += v0 * p0.x + v1 * q0.x;
        acc[1] += v0 * p0.y + v1 * q0.y;
        acc[2] += v0 * p1.x + v1 * q1.x;
        acc[3] += v0 * p1.y + v1 * q1.y;
        acc[4] += v0 * p2.x + v1 * q2.x;
        acc[5] += v0 * p2.y + v1 * q2.y;
        acc[6] += v0 * p3.x + v1 * q3.x;
        acc[7] += v0 * p3.y + v1 * q3.y;
    }
    for (; e < s1; e += 2) {
        int2 ev = g_edge[e];
        uint4 r0 = sup[(size_t)ev.x * 16 + hl];
        float v = __int_as_float(ev.y);
        float2 p0 = __half22float2(*(const __half2*)&r0.x);
        float2 p1 = __half22float2(*(const __half2*)&r0.y);
        float2 p2 = __half22float2(*(const __half2*)&r0.z);
        float2 p3 = __half22float2(*(const __half2*)&r0.w);
        acc[0] += v * p0.x; acc[1] += v * p0.y;
        acc[2] += v * p1.x; acc[3] += v * p1.y;
        acc[4] += v * p2.x; acc[5] += v * p2.y;
        acc[6] += v * p3.x; acc[7] += v * p3.y;
    }

#pragma unroll
    for (int j = 0; j < 8; j++)
        acc[j] += __shfl_xor_sync(0xffffffffu, acc[j], 16);

    if (half == 0) {
        float4* o = reinterpret_cast<float4*>(out + (size_t)row * HID + hl * 8);
        o[0] = make_float4(acc[0], acc[1], acc[2], acc[3]);
        o[1] = make_float4(acc[4], acc[5], acc[6], acc[7]);
    }
}

// ---------------------------------------------------------------------------
// Side stream + events, created ONCE (no device-mem allocation APIs).
// ---------------------------------------------------------------------------
struct AuxStreams {
    cudaStream_t s  = nullptr;
    cudaEvent_t  e1 = nullptr, e2 = nullptr;
    bool ok = false;
    AuxStreams() {
        if (cudaStreamCreateWithFlags(&s, cudaStreamNonBlocking) != cudaSuccess) { s = nullptr; return; }
        if (cudaEventCreateWithFlags(&e1, cudaEventDisableTiming) != cudaSuccess) { e1 = nullptr; return; }
        if (cudaEventCreateWithFlags(&e2, cudaEventDisableTiming) != cudaSuccess) { e2 = nullptr; return; }
        ok = true;
    }
};
static AuxStreams g_aux;

// ---------------------------------------------------------------------------
// Launch: inputs: x, adj_row, adj_col, adj_val, W, b
// Graph:  main: gemm -----------------.-> gather (also re-zeroes g_cnt)
//         side: hist -> scan -> fill -'
// ---------------------------------------------------------------------------
extern "C" void kernel_launch(void* const* d_in, const int* in_sizes, int n_in,
                              void* d_out, int out_size)
{
    const float* x       = (const float*)d_in[0];
    const int*   adj_row = (const int*)  d_in[1];
    const int*   adj_col = (const int*)  d_in[2];
    const float* adj_val = (const float*)d_in[3];
    const float* W       = (const float*)d_in[4];
    const float* b       = (const float*)d_in[5];
    float*       out     = (float*)d_out;

    const int n_nodes = in_sizes[0] / IN_F;
    const int n_edges = in_sizes[1];
    const int n_sb    = (n_nodes + SCAN_B - 1) / SCAN_B;
    const int gemm_blocks = (n_nodes + TILE_M - 1) / TILE_M;

    cudaFuncSetAttribute(gcn_linear_tf32_kernel,
                         cudaFuncAttributeMaxDynamicSharedMemorySize, GEMM_SMEM);

    const bool par = g_aux.ok;
    cudaStream_t sbin = par ? g_aux.s : (cudaStream_t)0;

    if (par) {
        cudaEventRecord(g_aux.e1, 0);
        cudaStreamWaitEvent(sbin, g_aux.e1, 0);
    }

    gcn_linear_tf32_kernel<<<gemm_blocks, 256, GEMM_SMEM>>>(x, W, b, n_nodes);

    hist_kernel<<<(n_edges / 4 + 255) / 256, 256, 0, sbin>>>(adj_row, n_edges);
    scan_fused_kernel<<<n_sb, SCAN_B, 0, sbin>>>(n_sb, n_nodes);
    fill_kernel<<<(n_edges / 4 + 255) / 256, 256, 0, sbin>>>(adj_row, adj_col, adj_val, n_edges);

    if (par) {
        cudaEventRecord(g_aux.e2, sbin);
        cudaStreamWaitEvent(0, g_aux.e2, 0);
    }

    row_gather_kernel<<<(n_nodes * 32 + 255) / 256, 256>>>(out, n_nodes);
}

// round 17
// speedup vs baseline: 1.9238x; 1.0709x over previous
#include <cuda_runtime.h>
#include <cuda_bf16.h>
#include <cuda_fp16.h>
#include <cstdint>

#define IN_F 256
#define HID  128
#define TILE_M 128
#define MAX_NODES 50000
#define MAX_EDGES 800000
#define SCAN_B   256
#define KCH      32               // K per pipeline stage
#define NCH      (IN_F / KCH)     // 8 stages
#define SSTRIDE  36               // smem row stride in floats (36 % 32 == 4)

// Scratch (device globals; no device-memory allocation APIs anywhere).
// INVARIANT: g_cnt is all-zero at kernel_launch entry; scan_c re-zeroes it
// (safe: scan_a has already snapshotted all block sums into g_bsum).
__device__ __half g_support_h[MAX_NODES * HID];   // fp16 support
__device__ int    g_cnt[MAX_NODES];
__device__ int    g_row_start[MAX_NODES + 1];
__device__ int    g_rank[MAX_EDGES];              // within-row rank per edge
__device__ int2   g_edge[MAX_EDGES];
__device__ int    g_bsum[SCAN_B];

// ---------------------------------------------------------------------------
// Helpers (plain sm_80-era PTX; nothing arch-'a' gated)
// ---------------------------------------------------------------------------
__device__ __forceinline__ uint32_t smem_to_u32(const void* p) {
    uint32_t a;
    asm("{ .reg .u64 t; cvta.to.shared.u64 t, %1; cvt.u32.u64 %0, t; }"
        : "=r"(a) : "l"(p));
    return a;
}

__device__ __forceinline__ uint32_t f2tf32(float f) {
    uint32_t r;
    asm("cvt.rna.tf32.f32 %0, %1;" : "=r"(r) : "f"(f));
    return r;
}

__device__ __forceinline__ void mma_tf32(float* c, const uint32_t* a,
                                         uint32_t b0, uint32_t b1) {
    asm volatile("mma.sync.aligned.m16n8k8.row.col.f32.tf32.tf32.f32 "
        "{%0,%1,%2,%3}, {%4,%5,%6,%7}, {%8,%9}, {%0,%1,%2,%3};"
        : "+f"(c[0]), "+f"(c[1]), "+f"(c[2]), "+f"(c[3])
        : "r"(a[0]), "r"(a[1]), "r"(a[2]), "r"(a[3]), "r"(b0), "r"(b1));
}

#define CP_ASYNC16(dst, src) \
    asm volatile("cp.async.cg.shared.global [%0], [%1], 16;" \
                 :: "r"(dst), "l"(src) : "memory")
#define CP_ASYNC16G(dst, src, sz) \
    asm volatile("cp.async.cg.shared.global [%0], [%1], 16, %2;" \
                 :: "r"(dst), "l"(src), "r"(sz) : "memory")
#define CP_COMMIT() asm volatile("cp.async.commit_group;" ::: "memory")
#define CP_WAIT(n)  asm volatile("cp.async.wait_group %0;" :: "n"(n) : "memory")

#define HALF_STAGE (TILE_M * SSTRIDE * 4)     // 18432 B (one of A or B)
#define STAGE_BYTES (2 * HALF_STAGE)          // 36864 B (A + B)
#define GEMM_SMEM (2 * STAGE_BYTES)           // 73728 B, occ 2

// ---------------------------------------------------------------------------
// GEMM: support = x @ W^T + b via single-pass tf32 mma (m16n8k8),
// two-stage cp.async pipeline over 8 K-chunks of 32. (unchanged from R13)
// ---------------------------------------------------------------------------
__global__ __launch_bounds__(256, 2) void gcn_linear_tf32_kernel(
    const float* __restrict__ x,
    const float* __restrict__ W,
    const float* __restrict__ b,
    int n_nodes)
{
    extern __shared__ char smem[];
    const uint32_t sbase = smem_to_u32(smem);

    const int t    = threadIdx.x;
    const int wid  = t >> 5;
    const int lane = t & 31;
    const int gid  = lane >> 2;          // 0..7
    const int tig  = lane & 3;           // 0..3
    const int row0 = blockIdx.x * TILE_M;

    const int wm = (wid & 3) * 32;
    const int wn = (wid >> 2) * 64;

    float acc[2][8][4];
#pragma unroll
    for (int mt = 0; mt < 2; mt++)
#pragma unroll
        for (int nt = 0; nt < 8; nt++)
#pragma unroll
            for (int j = 0; j < 4; j++) acc[mt][nt][j] = 0.0f;

    auto issue = [&](int c, int s) {
        uint32_t aBase = sbase + (uint32_t)s * STAGE_BYTES;
        uint32_t bBase = aBase + HALF_STAGE;
#pragma unroll
        for (int i = 0; i < 4; i++) {
            int idx = t + i * 256;              // 0..1023
            int n   = idx >> 3;                 // tile row 0..127
            int kq  = idx & 7;                  // float4 group 0..7
            uint32_t doff = (uint32_t)(n * SSTRIDE + kq * 4) * 4;
            int grow = row0 + n;
            const float* asrc = x + (size_t)grow * IN_F + c * KCH + kq * 4;
            int asz = (grow < n_nodes) ? 16 : 0;
            CP_ASYNC16G(aBase + doff, asrc, asz);
            const float* bsrc = W + n * IN_F + c * KCH + kq * 4;
            CP_ASYNC16(bBase + doff, bsrc);
        }
        CP_COMMIT();
    };

    issue(0, 0);

    for (int c = 0; c < NCH; c++) {
        const int cur = c & 1;
        if (c + 1 < NCH) {
            issue(c + 1, cur ^ 1);
            CP_WAIT(1);
        } else {
            CP_WAIT(0);
        }
        __syncthreads();

        const float* As = (const float*)(smem + (size_t)cur * STAGE_BYTES);
        const float* Bs = (const float*)(smem + (size_t)cur * STAGE_BYTES + HALF_STAGE);

#pragma unroll
        for (int ks = 0; ks < KCH / 8; ks++) {   // 4 K8 steps
            uint32_t a[2][4];
#pragma unroll
            for (int mt = 0; mt < 2; mt++) {
                int r0 = wm + mt * 16 + gid;
                int kc = ks * 8 + tig;
                a[mt][0] = f2tf32(As[r0 * SSTRIDE + kc]);
                a[mt][1] = f2tf32(As[(r0 + 8) * SSTRIDE + kc]);
                a[mt][2] = f2tf32(As[r0 * SSTRIDE + kc + 4]);
                a[mt][3] = f2tf32(As[(r0 + 8) * SSTRIDE + kc + 4]);
            }
#pragma unroll
            for (int ng = 0; ng < 8; ng++) {
                int nr = wn + ng * 8 + gid;
                int kc = ks * 8 + tig;
                uint32_t b0 = f2tf32(Bs[nr * SSTRIDE + kc]);
                uint32_t b1 = f2tf32(Bs[nr * SSTRIDE + kc + 4]);
                mma_tf32(acc[0][ng], a[0], b0, b1);
                mma_tf32(acc[1][ng], a[1], b0, b1);
            }
        }
        __syncthreads();
    }

    // ---- epilogue: bias + fp16 store (C frag: rows gid/gid+8, cols 2*tig) ----
#pragma unroll
    for (int nt = 0; nt < 8; nt++) {
        int col = wn + nt * 8 + 2 * tig;
        float2 bb = *(const float2*)(b + col);
#pragma unroll
        for (int mt = 0; mt < 2; mt++) {
            int r0g = row0 + wm + mt * 16 + gid;
            if (r0g < n_nodes) {
                __half2 h0 = __floats2half2_rn(acc[mt][nt][0] + bb.x,
                                               acc[mt][nt][1] + bb.y);
                *(__half2*)(g_support_h + (size_t)r0g * HID + col) = h0;
            }
            int r1g = r0g + 8;
            if (r1g < n_nodes) {
                __half2 h1 = __floats2half2_rn(acc[mt][nt][2] + bb.x,
                                               acc[mt][nt][3] + bb.y);
                *(__half2*)(g_support_h + (size_t)r1g * HID + col) = h1;
            }
        }
    }
}

// ---------------------------------------------------------------------------
// hist_rank: histogram AND capture each edge's within-row rank (the atomic's
// return value). The only atomic pass in the pipeline.
// ---------------------------------------------------------------------------
__global__ __launch_bounds__(256) void hist_rank_kernel(
    const int* __restrict__ adj_row, int n_edges)
{
    int base = (blockIdx.x * blockDim.x + threadIdx.x) * 4;
    if (base + 3 < n_edges) {
        int4 r = *(const int4*)(adj_row + base);
        int4 k;
        k.x = atomicAdd(&g_cnt[r.x], 1);
        k.y = atomicAdd(&g_cnt[r.y], 1);
        k.z = atomicAdd(&g_cnt[r.z], 1);
        k.w = atomicAdd(&g_cnt[r.w], 1);
        *(int4*)(g_rank + base) = k;
    } else {
        for (int e = base; e < n_edges; e++)
            g_rank[e] = atomicAdd(&g_cnt[adj_row[e]], 1);
    }
}

// scan_a: per-block reduce of g_cnt (256/block) -> g_bsum  (R13, proven)
__global__ __launch_bounds__(SCAN_B) void scan_a_kernel(int n_nodes)
{
    __shared__ int sm[SCAN_B / 32];
    const int t   = threadIdx.x;
    const int idx = blockIdx.x * SCAN_B + t;
    int v = (idx < n_nodes) ? g_cnt[idx] : 0;
#pragma unroll
    for (int o = 16; o > 0; o >>= 1) v += __shfl_down_sync(0xffffffffu, v, o);
    if ((t & 31) == 0) sm[t >> 5] = v;
    __syncthreads();
    if (t < 32) {
        int s = (t < SCAN_B / 32) ? sm[t] : 0;
#pragma unroll
        for (int o = 4; o > 0; o >>= 1) s += __shfl_down_sync(0xffffffffu, s, o);
        if (t == 0) g_bsum[blockIdx.x] = s;
    }
}

// scan_c: block prefix from g_bsum + local scan; writes row_start;
// re-zeroes g_cnt (safe: g_bsum snapshot complete).  (R13, proven)
__global__ __launch_bounds__(SCAN_B) void scan_c_kernel(int n_sb, int n_nodes)
{
    __shared__ int bs[SCAN_B];
    __shared__ int sm[SCAN_B];
    const int t   = threadIdx.x;
    const int idx = blockIdx.x * SCAN_B + t;

    int bv = (t < n_sb) ? g_bsum[t] : 0;
    bs[t] = bv;
    __syncthreads();
#pragma unroll
    for (int o = 1; o < SCAN_B; o <<= 1) {
        int u = (t >= o) ? bs[t - o] : 0;
        __syncthreads();
        bs[t] += u;
        __syncthreads();
    }
    const int blk_prefix = (blockIdx.x > 0) ? bs[blockIdx.x - 1] : 0;
    if (blockIdx.x == 0 && t == 0) g_row_start[n_nodes] = bs[n_sb - 1];

    int v = (idx < n_nodes) ? g_cnt[idx] : 0;
    sm[t] = v;
    __syncthreads();
#pragma unroll
    for (int o = 1; o < SCAN_B; o <<= 1) {
        int u = (t >= o) ? sm[t - o] : 0;
        __syncthreads();
        sm[t] += u;
        __syncthreads();
    }
    if (idx < n_nodes) {
        g_row_start[idx] = blk_prefix + sm[t] - v;
        g_cnt[idx]       = 0;            // restore zero-invariant
    }
}

// ---------------------------------------------------------------------------
// scatter: NO atomics — pos = row_start[r] + rank[e]. Fully independent
// loads/stores; latency-hidden. 4 edges/thread, vectorized input.
// ---------------------------------------------------------------------------
__global__ __launch_bounds__(256) void scatter_kernel(
    const int*   __restrict__ adj_row,
    const int*   __restrict__ adj_col,
    const float* __restrict__ adj_val,
    int n_edges)
{
    int base = (blockIdx.x * blockDim.x + threadIdx.x) * 4;
    if (base + 3 < n_edges) {
        int4   r = *(const int4*)(adj_row + base);
        int4   c = *(const int4*)(adj_col + base);
        float4 v = *(const float4*)(adj_val + base);
        int4   k = *(const int4*)(g_rank + base);
        g_edge[g_row_start[r.x] + k.x] = make_int2(c.x, __float_as_int(v.x));
        g_edge[g_row_start[r.y] + k.y] = make_int2(c.y, __float_as_int(v.y));
        g_edge[g_row_start[r.z] + k.z] = make_int2(c.z, __float_as_int(v.z));
        g_edge[g_row_start[r.w] + k.w] = make_int2(c.w, __float_as_int(v.w));
    } else {
        for (int e = base; e < n_edges; e++) {
            int r = adj_row[e];
            g_edge[g_row_start[r] + g_rank[e]] =
                make_int2(adj_col[e], __float_as_int(adj_val[e]));
        }
    }
}

// ---------------------------------------------------------------------------
// gather (R13 — best known): warp per row, half-warp per edge
// (16 lanes x uint4 = 256B row), shfl_xor(16) merge, no atomics.
// ---------------------------------------------------------------------------
__global__ __launch_bounds__(256) void row_gather_kernel(
    float* __restrict__ out, int n_nodes)
{
    const int row  = (blockIdx.x * blockDim.x + threadIdx.x) >> 5;
    const int lane = threadIdx.x & 31;
    const int half = lane >> 4;
    const int hl   = lane & 15;
    if (row >= n_nodes) return;

    const int s0 = g_row_start[row];
    const int s1 = g_row_start[row + 1];

    const uint4* sup = reinterpret_cast<const uint4*>(g_support_h);
    float acc[8];
#pragma unroll
    for (int j = 0; j < 8; j++) acc[j] = 0.0f;

    int e = s0 + half;
    for (; e + 2 < s1; e += 4) {
        int2 ev0 = g_edge[e];
        int2 ev1 = g_edge[e + 2];
        uint4 r0 = sup[(size_t)ev0.x * 16 + hl];
        uint4 r1 = sup[(size_t)ev1.x * 16 + hl];
        float v0 = __int_as_float(ev0.y);
        float v1 = __int_as_float(ev1.y);
        float2 p0 = __half22float2(*(const __half2*)&r0.x);
        float2 p1 = __half22float2(*(const __half2*)&r0.y);
        float2 p2 = __half22float2(*(const __half2*)&r0.z);
        float2 p3 = __half22float2(*(const __half2*)&r0.w);
        float2 q0 = __half22float2(*(const __half2*)&r1.x);
        float2 q1 = __half22float2(*(const __half2*)&r1.y);
        float2 q2 = __half22float2(*(const __half2*)&r1.z);
        float2 q3 = __half22float2(*(const __half2*)&r1.w);
        acc[0] += v0 * p0.x + v1 * q0.x;
        acc[1] += v0 * p0.y + v1 * q0.y;
        acc[2] += v0 * p1.x + v1 * q1.x;
        acc[3] += v0 * p1.y + v1 * q1.y;
        acc[4] += v0 * p2.x + v1 * q2.x;
        acc[5] += v0 * p2.y + v1 * q2.y;
        acc[6] += v0 * p3.x + v1 * q3.x;
        acc[7] += v0 * p3.y + v1 * q3.y;
    }
    for (; e < s1; e += 2) {
        int2 ev = g_edge[e];
        uint4 r0 = sup[(size_t)ev.x * 16 + hl];
        float v = __int_as_float(ev.y);
        float2 p0 = __half22float2(*(const __half2*)&r0.x);
        float2 p1 = __half22float2(*(const __half2*)&r0.y);
        float2 p2 = __half22float2(*(const __half2*)&r0.z);
        float2 p3 = __half22float2(*(const __half2*)&r0.w);
        acc[0] += v * p0.x; acc[1] += v * p0.y;
        acc[2] += v * p1.x; acc[3] += v * p1.y;
        acc[4] += v * p2.x; acc[5] += v * p2.y;
        acc[6] += v * p3.x; acc[7] += v * p3.y;
    }

#pragma unroll
    for (int j = 0; j < 8; j++)
        acc[j] += __shfl_xor_sync(0xffffffffu, acc[j], 16);

    if (half == 0) {
        float4* o = reinterpret_cast<float4*>(out + (size_t)row * HID + hl * 8);
        o[0] = make_float4(acc[0], acc[1], acc[2], acc[3]);
        o[1] = make_float4(acc[4], acc[5], acc[6], acc[7]);
    }
}

// ---------------------------------------------------------------------------
// Side stream + events, created ONCE (no device-mem allocation APIs).
// ---------------------------------------------------------------------------
struct AuxStreams {
    cudaStream_t s  = nullptr;
    cudaEvent_t  e1 = nullptr, e2 = nullptr;
    bool ok = false;
    AuxStreams() {
        if (cudaStreamCreateWithFlags(&s, cudaStreamNonBlocking) != cudaSuccess) { s = nullptr; return; }
        if (cudaEventCreateWithFlags(&e1, cudaEventDisableTiming) != cudaSuccess) { e1 = nullptr; return; }
        if (cudaEventCreateWithFlags(&e2, cudaEventDisableTiming) != cudaSuccess) { e2 = nullptr; return; }
        ok = true;
    }
};
static AuxStreams g_aux;

// ---------------------------------------------------------------------------
// Launch: inputs: x, adj_row, adj_col, adj_val, W, b
// Graph:  main: gemm ------------------------------------.-> gather
//         side: hist_rank -> scan_a -> scan_c -> scatter -'
// ---------------------------------------------------------------------------
extern "C" void kernel_launch(void* const* d_in, const int* in_sizes, int n_in,
                              void* d_out, int out_size)
{
    const float* x       = (const float*)d_in[0];
    const int*   adj_row = (const int*)  d_in[1];
    const int*   adj_col = (const int*)  d_in[2];
    const float* adj_val = (const float*)d_in[3];
    const float* W       = (const float*)d_in[4];
    const float* b       = (const float*)d_in[5];
    float*       out     = (float*)d_out;

    const int n_nodes = in_sizes[0] / IN_F;
    const int n_edges = in_sizes[1];
    const int n_sb    = (n_nodes + SCAN_B - 1) / SCAN_B;
    const int gemm_blocks = (n_nodes + TILE_M - 1) / TILE_M;

    cudaFuncSetAttribute(gcn_linear_tf32_kernel,
                         cudaFuncAttributeMaxDynamicSharedMemorySize, GEMM_SMEM);

    const bool par = g_aux.ok;
    cudaStream_t sbin = par ? g_aux.s : (cudaStream_t)0;

    if (par) {
        cudaEventRecord(g_aux.e1, 0);
        cudaStreamWaitEvent(sbin, g_aux.e1, 0);
    }

    gcn_linear_tf32_kernel<<<gemm_blocks, 256, GEMM_SMEM>>>(x, W, b, n_nodes);

    hist_rank_kernel<<<(n_edges / 4 + 255) / 256, 256, 0, sbin>>>(adj_row, n_edges);
    scan_a_kernel<<<n_sb, SCAN_B, 0, sbin>>>(n_nodes);
    scan_c_kernel<<<n_sb, SCAN_B, 0, sbin>>>(n_sb, n_nodes);
    scatter_kernel<<<(n_edges / 4 + 255) / 256, 256, 0, sbin>>>(adj_row, adj_col, adj_val, n_edges);

    if (par) {
        cudaEventRecord(g_aux.e2, sbin);
        cudaStreamWaitEvent(0, g_aux.e2, 0);
    }

    row_gather_kernel<<<(n_nodes * 32 + 255) / 256, 256>>>(out, n_nodes);
}